// round 8
// baseline (speedup 1.0000x reference)
#include <cuda_runtime.h>
#include <cuda_bf16.h>
#include <math.h>

// Problem constants
#define NMAX 50000
#define EMAX 800000
#define HDIM 128
#define GCNT 128
#define CCNT 10
#define SCAN_BLK 512

// ---------------- device scratch (no cudaMalloc allowed) ----------------
__device__ unsigned g_hb[NMAX * 64];    // h as packed bf16x2 (64 uint32 per row)
__device__ float g_agg[NMAX * HDIM];    // aggregated features (fp32, GEMM input)
__device__ float g_h3[NMAX * 16];
__device__ float g_deg[NMAX];
__device__ float g_dinv[NMAX];
__device__ int   g_cnt[NMAX];
__device__ int   g_row[NMAX + 1];
__device__ int   g_cur[NMAX];
__device__ int   g_bsum[128];
__device__ int   g_boff[128];
__device__ int   g_esrc[EMAX];
__device__ float g_ew2[EMAX];
__device__ float g_psum[GCNT * CCNT];
__device__ float g_pcnt[GCNT];

// ---------------- preprocessing ----------------

__global__ void k_init(int n) {
    int i = blockIdx.x * blockDim.x + threadIdx.x;
    if (i < n) { g_deg[i] = 1.0f; g_cnt[i] = 0; }
    if (i < GCNT * CCNT) g_psum[i] = 0.0f;
    if (i < GCNT) g_pcnt[i] = 0.0f;
}

__global__ void k_count(const int* __restrict__ dst, const float* __restrict__ ew, int e) {
    int i = blockIdx.x * blockDim.x + threadIdx.x;
    if (i >= e) return;
    int d = dst[i];
    atomicAdd(&g_deg[d], ew[i]);
    atomicAdd(&g_cnt[d], 1);
}

__global__ void k_scan1(int n) {
    __shared__ int sd[SCAN_BLK];
    int tid = threadIdx.x;
    int i = blockIdx.x * SCAN_BLK + tid;
    int v = (i < n) ? g_cnt[i] : 0;
    sd[tid] = v;
    __syncthreads();
#pragma unroll
    for (int off = 1; off < SCAN_BLK; off <<= 1) {
        int t = (tid >= off) ? sd[tid - off] : 0;
        __syncthreads();
        sd[tid] += t;
        __syncthreads();
    }
    if (i < n) g_row[i] = sd[tid] - v;
    if (tid == SCAN_BLK - 1) g_bsum[blockIdx.x] = sd[SCAN_BLK - 1];
}

__global__ void k_scan2(int nb, int n, int e) {
    __shared__ int sd[128];
    int tid = threadIdx.x;
    int v = (tid < nb) ? g_bsum[tid] : 0;
    sd[tid] = v;
    __syncthreads();
#pragma unroll
    for (int off = 1; off < 128; off <<= 1) {
        int t = (tid >= off) ? sd[tid - off] : 0;
        __syncthreads();
        sd[tid] += t;
        __syncthreads();
    }
    if (tid < nb) g_boff[tid] = sd[tid] - v;
    if (tid == 0) g_row[n] = e;
}

__global__ void k_scan3(int n) {
    int i = blockIdx.x * SCAN_BLK + threadIdx.x;
    if (i < n) {
        int r = g_row[i] + g_boff[blockIdx.x];
        g_row[i] = r;
        g_cur[i] = r;
        float d = g_deg[i];
        g_dinv[i] = (d > 0.0f) ? rsqrtf(d) : 0.0f;
    }
}

__global__ void k_scatter(const int* __restrict__ src, const int* __restrict__ dst,
                          const float* __restrict__ ew, int e) {
    int i = blockIdx.x * blockDim.x + threadIdx.x;
    if (i >= e) return;
    int s = src[i], d = dst[i];
    int pos = atomicAdd(&g_cur[d], 1);
    g_esrc[pos] = s;
    g_ew2[pos] = ew[i] * g_dinv[s];
}

// ---------------- tensor-core GEMM (3xTF32): [M,128] @ [128,128] -> bf16x2 ----
// R3 mainloop (best measured); epilogue packs to bf16x2 into g_hb.
#define TF32_MASK 0xFFFFE000u

__device__ __forceinline__ void mma_tf32(float* c, const unsigned* a,
                                         unsigned b0, unsigned b1) {
    asm volatile(
        "mma.sync.aligned.m16n8k8.row.col.f32.tf32.tf32.f32 "
        "{%0,%1,%2,%3}, {%4,%5,%6,%7}, {%8,%9}, {%0,%1,%2,%3};\n"
        : "+f"(c[0]), "+f"(c[1]), "+f"(c[2]), "+f"(c[3])
        : "r"(a[0]), "r"(a[1]), "r"(a[2]), "r"(a[3]), "r"(b0), "r"(b1));
}

__global__ __launch_bounds__(256, 2)
void sgemm128_tf32(const float* __restrict__ A, const float* __restrict__ B,
                   unsigned* __restrict__ Cb, int M) {
    __shared__ float As[2][128][20];
    __shared__ float Bs[2][16][136];

    int tid  = threadIdx.x;
    int warp = tid >> 5;
    int lane = tid & 31;
    int g = lane >> 2;      // 0..7
    int t = lane & 3;       // 0..3
    int r0 = warp * 16;
    int rowBase = blockIdx.x * 128;

    int aRow = tid >> 1;          // 0..127
    int aOff = (tid & 1) * 8;     // 0 or 8
    int bRow = tid >> 4;          // 0..15
    int bOff = (tid & 15) * 8;    // 0..120

    bool aOk = (rowBase + aRow) < M;
    const float* Ap = A + (size_t)(aOk ? rowBase + aRow : 0) * 128;

    float acc[16][4];
#pragma unroll
    for (int j = 0; j < 16; j++)
#pragma unroll
        for (int q = 0; q < 4; q++) acc[j][q] = 0.0f;

    {
        float4 z = make_float4(0.f, 0.f, 0.f, 0.f);
        float4 a0 = aOk ? *(const float4*)(Ap + aOff)     : z;
        float4 a1 = aOk ? *(const float4*)(Ap + aOff + 4) : z;
        *(float4*)&As[0][aRow][aOff]     = a0;
        *(float4*)&As[0][aRow][aOff + 4] = a1;
        float4 b0 = *(const float4*)(B + (size_t)bRow * 128 + bOff);
        float4 b1 = *(const float4*)(B + (size_t)bRow * 128 + bOff + 4);
        *(float4*)&Bs[0][bRow][bOff]     = b0;
        *(float4*)&Bs[0][bRow][bOff + 4] = b1;
    }
    __syncthreads();

    int p = 0;
    for (int k0 = 0; k0 < 128; k0 += 16) {
        bool more = (k0 + 16) < 128;
        float4 pa0, pa1, pb0, pb1;
        if (more) {
            float4 z = make_float4(0.f, 0.f, 0.f, 0.f);
            pa0 = aOk ? *(const float4*)(Ap + k0 + 16 + aOff)     : z;
            pa1 = aOk ? *(const float4*)(Ap + k0 + 16 + aOff + 4) : z;
            pb0 = *(const float4*)(B + (size_t)(k0 + 16 + bRow) * 128 + bOff);
            pb1 = *(const float4*)(B + (size_t)(k0 + 16 + bRow) * 128 + bOff + 4);
        }

#pragma unroll
        for (int kk = 0; kk < 16; kk += 8) {
            float av0 = As[p][r0 + g    ][kk + t];
            float av1 = As[p][r0 + g + 8][kk + t];
            float av2 = As[p][r0 + g    ][kk + t + 4];
            float av3 = As[p][r0 + g + 8][kk + t + 4];
            unsigned ahi[4], alo[4];
            {
                float av[4] = {av0, av1, av2, av3};
#pragma unroll
                for (int q = 0; q < 4; q++) {
                    unsigned h = __float_as_uint(av[q]) & TF32_MASK;
                    ahi[q] = h;
                    alo[q] = __float_as_uint(av[q] - __uint_as_float(h));
                }
            }
#pragma unroll
            for (int j = 0; j < 16; j++) {
                float bv0 = Bs[p][kk + t    ][j * 8 + g];
                float bv1 = Bs[p][kk + t + 4][j * 8 + g];
                unsigned bh0 = __float_as_uint(bv0) & TF32_MASK;
                unsigned bh1 = __float_as_uint(bv1) & TF32_MASK;
                unsigned bl0 = __float_as_uint(bv0 - __uint_as_float(bh0));
                unsigned bl1 = __float_as_uint(bv1 - __uint_as_float(bh1));
                mma_tf32(acc[j], ahi, bh0, bh1);
                mma_tf32(acc[j], ahi, bl0, bl1);
                mma_tf32(acc[j], alo, bh0, bh1);
            }
        }

        if (more) {
            int q = p ^ 1;
            *(float4*)&As[q][aRow][aOff]     = pa0;
            *(float4*)&As[q][aRow][aOff + 4] = pa1;
            *(float4*)&Bs[q][bRow][bOff]     = pb0;
            *(float4*)&Bs[q][bRow][bOff + 4] = pb1;
            __syncthreads();
            p = q;
        }
    }

    // epilogue: pack (c0,c1)=(cols 2t,2t+1) and (c2,c3) into bf16x2 words
    int rA = rowBase + r0 + g;
    int rB = rA + 8;
#pragma unroll
    for (int j = 0; j < 16; j++) {
        int widx = j * 4 + t;   // uint32 index within the 64-word row
        if (rA < M) {
            __nv_bfloat162 v = __float22bfloat162_rn(make_float2(acc[j][0], acc[j][1]));
            Cb[(size_t)rA * 64 + widx] = *(unsigned*)&v;
        }
        if (rB < M) {
            __nv_bfloat162 v = __float22bfloat162_rn(make_float2(acc[j][2], acc[j][3]));
            Cb[(size_t)rB * 64 + widx] = *(unsigned*)&v;
        }
    }
}

// ---------------- aggregation: gathers bf16, accumulates fp32 ----------------
// one warp per node; lane handles cols 4l..4l+3 = uint32 words 2l, 2l+1 (8B/lane)
__global__ __launch_bounds__(256)
void agg_h128(const unsigned* __restrict__ hb, float* __restrict__ out,
              const float* __restrict__ bias, int do_relu, int n) {
    int gw = (blockIdx.x * blockDim.x + threadIdx.x) >> 5;
    if (gw >= n) return;
    int lane = threadIdx.x & 31;
    const uint2* h2 = (const uint2*)hb;   // 32 uint2 per row

    float di = g_dinv[gw];
    float4 acc;
    {
        uint2 u = h2[(size_t)gw * 32 + lane];
        float2 f0 = __bfloat1622float2(*(const __nv_bfloat162*)&u.x);
        float2 f1 = __bfloat1622float2(*(const __nv_bfloat162*)&u.y);
        acc.x = f0.x * di; acc.y = f0.y * di;
        acc.z = f1.x * di; acc.w = f1.y * di;
    }

    int j = g_row[gw];
    int end = g_row[gw + 1];
    for (; j + 4 <= end; j += 4) {
        int s0 = g_esrc[j], s1 = g_esrc[j + 1], s2 = g_esrc[j + 2], s3 = g_esrc[j + 3];
        float w0 = g_ew2[j], w1 = g_ew2[j + 1], w2 = g_ew2[j + 2], w3 = g_ew2[j + 3];
        uint2 u0 = h2[(size_t)s0 * 32 + lane];
        uint2 u1 = h2[(size_t)s1 * 32 + lane];
        uint2 u2 = h2[(size_t)s2 * 32 + lane];
        uint2 u3 = h2[(size_t)s3 * 32 + lane];
        float2 a0 = __bfloat1622float2(*(const __nv_bfloat162*)&u0.x);
        float2 b0 = __bfloat1622float2(*(const __nv_bfloat162*)&u0.y);
        float2 a1 = __bfloat1622float2(*(const __nv_bfloat162*)&u1.x);
        float2 b1 = __bfloat1622float2(*(const __nv_bfloat162*)&u1.y);
        float2 a2 = __bfloat1622float2(*(const __nv_bfloat162*)&u2.x);
        float2 b2 = __bfloat1622float2(*(const __nv_bfloat162*)&u2.y);
        float2 a3 = __bfloat1622float2(*(const __nv_bfloat162*)&u3.x);
        float2 b3 = __bfloat1622float2(*(const __nv_bfloat162*)&u3.y);
        acc.x = fmaf(w0, a0.x, acc.x); acc.y = fmaf(w0, a0.y, acc.y);
        acc.z = fmaf(w0, b0.x, acc.z); acc.w = fmaf(w0, b0.y, acc.w);
        acc.x = fmaf(w1, a1.x, acc.x); acc.y = fmaf(w1, a1.y, acc.y);
        acc.z = fmaf(w1, b1.x, acc.z); acc.w = fmaf(w1, b1.y, acc.w);
        acc.x = fmaf(w2, a2.x, acc.x); acc.y = fmaf(w2, a2.y, acc.y);
        acc.z = fmaf(w2, b2.x, acc.z); acc.w = fmaf(w2, b2.y, acc.w);
        acc.x = fmaf(w3, a3.x, acc.x); acc.y = fmaf(w3, a3.y, acc.y);
        acc.z = fmaf(w3, b3.x, acc.z); acc.w = fmaf(w3, b3.y, acc.w);
    }
    for (; j < end; j++) {
        int s = g_esrc[j];
        float w = g_ew2[j];
        uint2 u = h2[(size_t)s * 32 + lane];
        float2 f0 = __bfloat1622float2(*(const __nv_bfloat162*)&u.x);
        float2 f1 = __bfloat1622float2(*(const __nv_bfloat162*)&u.y);
        acc.x = fmaf(w, f0.x, acc.x); acc.y = fmaf(w, f0.y, acc.y);
        acc.z = fmaf(w, f1.x, acc.z); acc.w = fmaf(w, f1.y, acc.w);
    }

    float4 bb = ((const float4*)bias)[lane];
    acc.x = fmaf(acc.x, di, bb.x);
    acc.y = fmaf(acc.y, di, bb.y);
    acc.z = fmaf(acc.z, di, bb.z);
    acc.w = fmaf(acc.w, di, bb.w);
    if (do_relu) {
        acc.x = fmaxf(acc.x, 0.f); acc.y = fmaxf(acc.y, 0.f);
        acc.z = fmaxf(acc.z, 0.f); acc.w = fmaxf(acc.w, 0.f);
    }
    ((float4*)out)[(size_t)gw * 32 + lane] = acc;
}

// ---------------- layer 3 projection ----------------
__global__ __launch_bounds__(512)
void gemm_w3(const float* __restrict__ A, const float* __restrict__ W, int M) {
    __shared__ float xs[32][128];
    __shared__ float Ws[128 * CCNT];
    int tid = threadIdx.x;
    int r0 = blockIdx.x * 32;

    for (int t = tid; t < 1024; t += 512) {
        int r = t >> 5;
        int c4 = (t & 31) << 2;
        int grow = r0 + r;
        float4 v = make_float4(0.f, 0.f, 0.f, 0.f);
        if (grow < M) v = *(const float4*)(A + (size_t)grow * 128 + c4);
        *(float4*)&xs[r][c4] = v;
    }
    for (int t = tid; t < 128 * CCNT; t += 512) Ws[t] = W[t];
    __syncthreads();

    int r = tid >> 4;
    int c = tid & 15;
    if (c < CCNT) {
        float acc = 0.0f;
#pragma unroll
        for (int k = 0; k < 128; k++)
            acc = fmaf(xs[r][k], Ws[k * CCNT + c], acc);
        int grow = r0 + r;
        if (grow < M) g_h3[grow * 16 + c] = acc;
    }
}

// ---------------- layer 3 aggregation + pool ----------------
__global__ __launch_bounds__(256)
void agg_c16_pool(const int* __restrict__ batch, const float* __restrict__ b3, int n) {
    int gw = (blockIdx.x * blockDim.x + threadIdx.x) >> 5;
    if (gw >= n) return;
    int lane = threadIdx.x & 31;
    bool active = (lane < CCNT);

    float di = g_dinv[gw];
    float acc = 0.0f;
    if (active) acc = g_h3[gw * 16 + lane] * di;

    int j = g_row[gw];
    int end = g_row[gw + 1];
    for (; j + 4 <= end; j += 4) {
        int s0 = g_esrc[j], s1 = g_esrc[j + 1], s2 = g_esrc[j + 2], s3 = g_esrc[j + 3];
        float w0 = g_ew2[j], w1 = g_ew2[j + 1], w2 = g_ew2[j + 2], w3 = g_ew2[j + 3];
        if (active) {
            acc = fmaf(w0, g_h3[s0 * 16 + lane], acc);
            acc = fmaf(w1, g_h3[s1 * 16 + lane], acc);
            acc = fmaf(w2, g_h3[s2 * 16 + lane], acc);
            acc = fmaf(w3, g_h3[s3 * 16 + lane], acc);
        }
    }
    for (; j < end; j++) {
        int s = g_esrc[j];
        float w = g_ew2[j];
        if (active) acc = fmaf(w, g_h3[s * 16 + lane], acc);
    }

    int g = batch[gw];
    if (active) {
        acc = fmaf(acc, di, b3[lane]);
        atomicAdd(&g_psum[g * CCNT + lane], acc);
    }
    if (lane == 0) atomicAdd(&g_pcnt[g], 1.0f);
}

// ---------------- final: mean + log_softmax ----------------
__global__ void k_finalize(float* __restrict__ out) {
    int g = threadIdx.x;
    if (g >= GCNT) return;
    float c = fmaxf(g_pcnt[g], 1.0f);
    float v[CCNT];
    float m = -1e30f;
#pragma unroll
    for (int j = 0; j < CCNT; j++) {
        v[j] = g_psum[g * CCNT + j] / c;
        m = fmaxf(m, v[j]);
    }
    float s = 0.0f;
#pragma unroll
    for (int j = 0; j < CCNT; j++) s += expf(v[j] - m);
    float lse = logf(s) + m;
#pragma unroll
    for (int j = 0; j < CCNT; j++) out[g * CCNT + j] = v[j] - lse;
}

// ---------------- launch ----------------
extern "C" void kernel_launch(void* const* d_in, const int* in_sizes, int n_in,
                              void* d_out, int out_size) {
    const float* x    = (const float*)d_in[0];
    const int*   ei   = (const int*)d_in[1];
    const float* ea   = (const float*)d_in[2];
    const int*   bat  = (const int*)d_in[3];
    const float* W1   = (const float*)d_in[4];
    const float* b1   = (const float*)d_in[5];
    const float* W2   = (const float*)d_in[6];
    const float* b2   = (const float*)d_in[7];
    const float* W3   = (const float*)d_in[8];
    const float* b3   = (const float*)d_in[9];
    float* out = (float*)d_out;

    int n = in_sizes[0] / HDIM;   // 50000
    int e = in_sizes[1] / 2;      // 800000
    const int* src = ei;
    const int* dst = ei + e;

    unsigned* ghb;
    float* gagg;
    cudaGetSymbolAddress((void**)&ghb, g_hb);
    cudaGetSymbolAddress((void**)&gagg, g_agg);

    int nb = (n + SCAN_BLK - 1) / SCAN_BLK;
    int gemmBlocks = (n + 127) / 128;
    int aggBlocks = (n * 32 + 255) / 256;

    cudaStream_t s0 = (cudaStream_t)0;

    // fork a side stream: layer-1 GEMM is independent of CSR preprocessing
    cudaStream_t s2;
    cudaStreamCreateWithFlags(&s2, cudaStreamNonBlocking);
    cudaEvent_t evFork, evJoin;
    cudaEventCreateWithFlags(&evFork, cudaEventDisableTiming);
    cudaEventCreateWithFlags(&evJoin, cudaEventDisableTiming);

    cudaEventRecord(evFork, s0);
    cudaStreamWaitEvent(s2, evFork, 0);
    sgemm128_tf32<<<gemmBlocks, 256, 0, s2>>>(x, W1, ghb, n);   // h = x@W1 (bf16 packed)
    cudaEventRecord(evJoin, s2);

    // preprocessing on main stream (concurrent with the GEMM above)
    k_init<<<(n + 255) / 256, 256, 0, s0>>>(n);
    k_count<<<(e + 255) / 256, 256, 0, s0>>>(dst, ea, e);
    k_scan1<<<nb, SCAN_BLK, 0, s0>>>(n);
    k_scan2<<<1, 128, 0, s0>>>(nb, n, e);
    k_scan3<<<nb, SCAN_BLK, 0, s0>>>(n);
    k_scatter<<<(e + 255) / 256, 256, 0, s0>>>(src, dst, ea, e);

    // join: aggregation needs both CSR and h
    cudaStreamWaitEvent(s0, evJoin, 0);
    agg_h128<<<aggBlocks, 256, 0, s0>>>(ghb, gagg, b1, 1, n);

    // layer 2
    sgemm128_tf32<<<gemmBlocks, 256, 0, s0>>>(gagg, W2, ghb, n);
    agg_h128<<<aggBlocks, 256, 0, s0>>>(ghb, gagg, b2, 1, n);

    // layer 3: project to C first, then aggregate + pool
    gemm_w3<<<(n + 31) / 32, 512, 0, s0>>>(gagg, W3, n);
    agg_c16_pool<<<aggBlocks, 256, 0, s0>>>(bat, b3, n);

    k_finalize<<<1, 128, 0, s0>>>(out);
    // NOTE: s2/events intentionally not destroyed — kernel_launch is invoked
    // only for the correctness run and one graph capture.
}

// round 9
// speedup vs baseline: 1.4429x; 1.4429x over previous
#include <cuda_runtime.h>
#include <cuda_bf16.h>
#include <math.h>

// Problem constants
#define NMAX 50000
#define EMAX 800000
#define HDIM 128
#define GCNT 128
#define CCNT 10
#define SCAN_BLK 512

// ---------------- device scratch (no cudaMalloc allowed) ----------------
__device__ unsigned g_hb[NMAX * 64];    // h as packed bf16x2 (64 uint32 per row)
__device__ float g_agg[NMAX * HDIM];    // aggregated features (fp32, GEMM input)
__device__ float g_h3[NMAX * 16];
__device__ float g_deg[NMAX];
__device__ float g_dinv[NMAX];
__device__ int   g_cnt[NMAX];
__device__ int   g_row[NMAX + 1];
__device__ int   g_cur[NMAX];
__device__ int   g_bsum[128];
__device__ int   g_boff[128];
__device__ int   g_esrc[EMAX];
__device__ float g_ew2[EMAX];
__device__ float g_psum[GCNT * CCNT];
__device__ float g_pcnt[GCNT];

// ---------------- preprocessing ----------------

__global__ void k_init(int n) {
    int i = blockIdx.x * blockDim.x + threadIdx.x;
    if (i < n) { g_deg[i] = 1.0f; g_cnt[i] = 0; }
    if (i < GCNT * CCNT) g_psum[i] = 0.0f;
    if (i < GCNT) g_pcnt[i] = 0.0f;
}

__global__ void k_count(const int* __restrict__ dst, const float* __restrict__ ew, int e) {
    int i = blockIdx.x * blockDim.x + threadIdx.x;
    if (i >= e) return;
    int d = dst[i];
    atomicAdd(&g_deg[d], ew[i]);
    atomicAdd(&g_cnt[d], 1);
}

__global__ void k_scan1(int n) {
    __shared__ int sd[SCAN_BLK];
    int tid = threadIdx.x;
    int i = blockIdx.x * SCAN_BLK + tid;
    int v = (i < n) ? g_cnt[i] : 0;
    sd[tid] = v;
    __syncthreads();
#pragma unroll
    for (int off = 1; off < SCAN_BLK; off <<= 1) {
        int t = (tid >= off) ? sd[tid - off] : 0;
        __syncthreads();
        sd[tid] += t;
        __syncthreads();
    }
    if (i < n) g_row[i] = sd[tid] - v;
    if (tid == SCAN_BLK - 1) g_bsum[blockIdx.x] = sd[SCAN_BLK - 1];
}

__global__ void k_scan2(int nb, int n, int e) {
    __shared__ int sd[128];
    int tid = threadIdx.x;
    int v = (tid < nb) ? g_bsum[tid] : 0;
    sd[tid] = v;
    __syncthreads();
#pragma unroll
    for (int off = 1; off < 128; off <<= 1) {
        int t = (tid >= off) ? sd[tid - off] : 0;
        __syncthreads();
        sd[tid] += t;
        __syncthreads();
    }
    if (tid < nb) g_boff[tid] = sd[tid] - v;
    if (tid == 0) g_row[n] = e;
}

__global__ void k_scan3(int n) {
    int i = blockIdx.x * SCAN_BLK + threadIdx.x;
    if (i < n) {
        int r = g_row[i] + g_boff[blockIdx.x];
        g_row[i] = r;
        g_cur[i] = r;
        float d = g_deg[i];
        g_dinv[i] = (d > 0.0f) ? rsqrtf(d) : 0.0f;
    }
}

__global__ void k_scatter(const int* __restrict__ src, const int* __restrict__ dst,
                          const float* __restrict__ ew, int e) {
    int i = blockIdx.x * blockDim.x + threadIdx.x;
    if (i >= e) return;
    int s = src[i], d = dst[i];
    int pos = atomicAdd(&g_cur[d], 1);
    g_esrc[pos] = s;
    g_ew2[pos] = ew[i] * g_dinv[s];
}

// ---------------- tensor-core GEMM (3xTF32): [M,128] @ [128,128] -> bf16x2 ----
#define TF32_MASK 0xFFFFE000u

__device__ __forceinline__ void mma_tf32(float* c, const unsigned* a,
                                         unsigned b0, unsigned b1) {
    asm volatile(
        "mma.sync.aligned.m16n8k8.row.col.f32.tf32.tf32.f32 "
        "{%0,%1,%2,%3}, {%4,%5,%6,%7}, {%8,%9}, {%0,%1,%2,%3};\n"
        : "+f"(c[0]), "+f"(c[1]), "+f"(c[2]), "+f"(c[3])
        : "r"(a[0]), "r"(a[1]), "r"(a[2]), "r"(a[3]), "r"(b0), "r"(b1));
}

__global__ __launch_bounds__(256, 2)
void sgemm128_tf32(const float* __restrict__ A, const float* __restrict__ B,
                   unsigned* __restrict__ Cb, int M) {
    __shared__ float As[2][128][20];
    __shared__ float Bs[2][16][136];

    int tid  = threadIdx.x;
    int warp = tid >> 5;
    int lane = tid & 31;
    int g = lane >> 2;      // 0..7
    int t = lane & 3;       // 0..3
    int r0 = warp * 16;
    int rowBase = blockIdx.x * 128;

    int aRow = tid >> 1;          // 0..127
    int aOff = (tid & 1) * 8;     // 0 or 8
    int bRow = tid >> 4;          // 0..15
    int bOff = (tid & 15) * 8;    // 0..120

    bool aOk = (rowBase + aRow) < M;
    const float* Ap = A + (size_t)(aOk ? rowBase + aRow : 0) * 128;

    float acc[16][4];
#pragma unroll
    for (int j = 0; j < 16; j++)
#pragma unroll
        for (int q = 0; q < 4; q++) acc[j][q] = 0.0f;

    {
        float4 z = make_float4(0.f, 0.f, 0.f, 0.f);
        float4 a0 = aOk ? *(const float4*)(Ap + aOff)     : z;
        float4 a1 = aOk ? *(const float4*)(Ap + aOff + 4) : z;
        *(float4*)&As[0][aRow][aOff]     = a0;
        *(float4*)&As[0][aRow][aOff + 4] = a1;
        float4 b0 = *(const float4*)(B + (size_t)bRow * 128 + bOff);
        float4 b1 = *(const float4*)(B + (size_t)bRow * 128 + bOff + 4);
        *(float4*)&Bs[0][bRow][bOff]     = b0;
        *(float4*)&Bs[0][bRow][bOff + 4] = b1;
    }
    __syncthreads();

    int p = 0;
    for (int k0 = 0; k0 < 128; k0 += 16) {
        bool more = (k0 + 16) < 128;
        float4 pa0, pa1, pb0, pb1;
        if (more) {
            float4 z = make_float4(0.f, 0.f, 0.f, 0.f);
            pa0 = aOk ? *(const float4*)(Ap + k0 + 16 + aOff)     : z;
            pa1 = aOk ? *(const float4*)(Ap + k0 + 16 + aOff + 4) : z;
            pb0 = *(const float4*)(B + (size_t)(k0 + 16 + bRow) * 128 + bOff);
            pb1 = *(const float4*)(B + (size_t)(k0 + 16 + bRow) * 128 + bOff + 4);
        }

#pragma unroll
        for (int kk = 0; kk < 16; kk += 8) {
            float av0 = As[p][r0 + g    ][kk + t];
            float av1 = As[p][r0 + g + 8][kk + t];
            float av2 = As[p][r0 + g    ][kk + t + 4];
            float av3 = As[p][r0 + g + 8][kk + t + 4];
            unsigned ahi[4], alo[4];
            {
                float av[4] = {av0, av1, av2, av3};
#pragma unroll
                for (int q = 0; q < 4; q++) {
                    unsigned h = __float_as_uint(av[q]) & TF32_MASK;
                    ahi[q] = h;
                    alo[q] = __float_as_uint(av[q] - __uint_as_float(h));
                }
            }
#pragma unroll
            for (int j = 0; j < 16; j++) {
                float bv0 = Bs[p][kk + t    ][j * 8 + g];
                float bv1 = Bs[p][kk + t + 4][j * 8 + g];
                unsigned bh0 = __float_as_uint(bv0) & TF32_MASK;
                unsigned bh1 = __float_as_uint(bv1) & TF32_MASK;
                unsigned bl0 = __float_as_uint(bv0 - __uint_as_float(bh0));
                unsigned bl1 = __float_as_uint(bv1 - __uint_as_float(bh1));
                mma_tf32(acc[j], ahi, bh0, bh1);
                mma_tf32(acc[j], ahi, bl0, bl1);
                mma_tf32(acc[j], alo, bh0, bh1);
            }
        }

        if (more) {
            int q = p ^ 1;
            *(float4*)&As[q][aRow][aOff]     = pa0;
            *(float4*)&As[q][aRow][aOff + 4] = pa1;
            *(float4*)&Bs[q][bRow][bOff]     = pb0;
            *(float4*)&Bs[q][bRow][bOff + 4] = pb1;
            __syncthreads();
            p = q;
        }
    }

    int rA = rowBase + r0 + g;
    int rB = rA + 8;
#pragma unroll
    for (int j = 0; j < 16; j++) {
        int widx = j * 4 + t;
        if (rA < M) {
            __nv_bfloat162 v = __float22bfloat162_rn(make_float2(acc[j][0], acc[j][1]));
            Cb[(size_t)rA * 64 + widx] = *(unsigned*)&v;
        }
        if (rB < M) {
            __nv_bfloat162 v = __float22bfloat162_rn(make_float2(acc[j][2], acc[j][3]));
            Cb[(size_t)rB * 64 + widx] = *(unsigned*)&v;
        }
    }
}

// ---------------- aggregation: gathers bf16, accumulates fp32 ----------------
__global__ __launch_bounds__(256)
void agg_h128(const unsigned* __restrict__ hb, float* __restrict__ out,
              const float* __restrict__ bias, int do_relu, int n) {
    int gw = (blockIdx.x * blockDim.x + threadIdx.x) >> 5;
    if (gw >= n) return;
    int lane = threadIdx.x & 31;
    const uint2* h2 = (const uint2*)hb;

    float di = g_dinv[gw];
    float4 acc;
    {
        uint2 u = h2[(size_t)gw * 32 + lane];
        float2 f0 = __bfloat1622float2(*(const __nv_bfloat162*)&u.x);
        float2 f1 = __bfloat1622float2(*(const __nv_bfloat162*)&u.y);
        acc.x = f0.x * di; acc.y = f0.y * di;
        acc.z = f1.x * di; acc.w = f1.y * di;
    }

    int j = g_row[gw];
    int end = g_row[gw + 1];
    for (; j + 4 <= end; j += 4) {
        int s0 = g_esrc[j], s1 = g_esrc[j + 1], s2 = g_esrc[j + 2], s3 = g_esrc[j + 3];
        float w0 = g_ew2[j], w1 = g_ew2[j + 1], w2 = g_ew2[j + 2], w3 = g_ew2[j + 3];
        uint2 u0 = h2[(size_t)s0 * 32 + lane];
        uint2 u1 = h2[(size_t)s1 * 32 + lane];
        uint2 u2 = h2[(size_t)s2 * 32 + lane];
        uint2 u3 = h2[(size_t)s3 * 32 + lane];
        float2 a0 = __bfloat1622float2(*(const __nv_bfloat162*)&u0.x);
        float2 b0 = __bfloat1622float2(*(const __nv_bfloat162*)&u0.y);
        float2 a1 = __bfloat1622float2(*(const __nv_bfloat162*)&u1.x);
        float2 b1 = __bfloat1622float2(*(const __nv_bfloat162*)&u1.y);
        float2 a2 = __bfloat1622float2(*(const __nv_bfloat162*)&u2.x);
        float2 b2 = __bfloat1622float2(*(const __nv_bfloat162*)&u2.y);
        float2 a3 = __bfloat1622float2(*(const __nv_bfloat162*)&u3.x);
        float2 b3 = __bfloat1622float2(*(const __nv_bfloat162*)&u3.y);
        acc.x = fmaf(w0, a0.x, acc.x); acc.y = fmaf(w0, a0.y, acc.y);
        acc.z = fmaf(w0, b0.x, acc.z); acc.w = fmaf(w0, b0.y, acc.w);
        acc.x = fmaf(w1, a1.x, acc.x); acc.y = fmaf(w1, a1.y, acc.y);
        acc.z = fmaf(w1, b1.x, acc.z); acc.w = fmaf(w1, b1.y, acc.w);
        acc.x = fmaf(w2, a2.x, acc.x); acc.y = fmaf(w2, a2.y, acc.y);
        acc.z = fmaf(w2, b2.x, acc.z); acc.w = fmaf(w2, b2.y, acc.w);
        acc.x = fmaf(w3, a3.x, acc.x); acc.y = fmaf(w3, a3.y, acc.y);
        acc.z = fmaf(w3, b3.x, acc.z); acc.w = fmaf(w3, b3.y, acc.w);
    }
    for (; j < end; j++) {
        int s = g_esrc[j];
        float w = g_ew2[j];
        uint2 u = h2[(size_t)s * 32 + lane];
        float2 f0 = __bfloat1622float2(*(const __nv_bfloat162*)&u.x);
        float2 f1 = __bfloat1622float2(*(const __nv_bfloat162*)&u.y);
        acc.x = fmaf(w, f0.x, acc.x); acc.y = fmaf(w, f0.y, acc.y);
        acc.z = fmaf(w, f1.x, acc.z); acc.w = fmaf(w, f1.y, acc.w);
    }

    float4 bb = ((const float4*)bias)[lane];
    acc.x = fmaf(acc.x, di, bb.x);
    acc.y = fmaf(acc.y, di, bb.y);
    acc.z = fmaf(acc.z, di, bb.z);
    acc.w = fmaf(acc.w, di, bb.w);
    if (do_relu) {
        acc.x = fmaxf(acc.x, 0.f); acc.y = fmaxf(acc.y, 0.f);
        acc.z = fmaxf(acc.z, 0.f); acc.w = fmaxf(acc.w, 0.f);
    }
    ((float4*)out)[(size_t)gw * 32 + lane] = acc;
}

// ---------------- layer 3 projection ----------------
__global__ __launch_bounds__(512)
void gemm_w3(const float* __restrict__ A, const float* __restrict__ W, int M) {
    __shared__ float xs[32][128];
    __shared__ float Ws[128 * CCNT];
    int tid = threadIdx.x;
    int r0 = blockIdx.x * 32;

    for (int t = tid; t < 1024; t += 512) {
        int r = t >> 5;
        int c4 = (t & 31) << 2;
        int grow = r0 + r;
        float4 v = make_float4(0.f, 0.f, 0.f, 0.f);
        if (grow < M) v = *(const float4*)(A + (size_t)grow * 128 + c4);
        *(float4*)&xs[r][c4] = v;
    }
    for (int t = tid; t < 128 * CCNT; t += 512) Ws[t] = W[t];
    __syncthreads();

    int r = tid >> 4;
    int c = tid & 15;
    if (c < CCNT) {
        float acc = 0.0f;
#pragma unroll
        for (int k = 0; k < 128; k++)
            acc = fmaf(xs[r][k], Ws[k * CCNT + c], acc);
        int grow = r0 + r;
        if (grow < M) g_h3[grow * 16 + c] = acc;
    }
}

// ---------------- layer 3 aggregation + pool ----------------
__global__ __launch_bounds__(256)
void agg_c16_pool(const int* __restrict__ batch, const float* __restrict__ b3, int n) {
    int gw = (blockIdx.x * blockDim.x + threadIdx.x) >> 5;
    if (gw >= n) return;
    int lane = threadIdx.x & 31;
    bool active = (lane < CCNT);

    float di = g_dinv[gw];
    float acc = 0.0f;
    if (active) acc = g_h3[gw * 16 + lane] * di;

    int j = g_row[gw];
    int end = g_row[gw + 1];
    for (; j + 4 <= end; j += 4) {
        int s0 = g_esrc[j], s1 = g_esrc[j + 1], s2 = g_esrc[j + 2], s3 = g_esrc[j + 3];
        float w0 = g_ew2[j], w1 = g_ew2[j + 1], w2 = g_ew2[j + 2], w3 = g_ew2[j + 3];
        if (active) {
            acc = fmaf(w0, g_h3[s0 * 16 + lane], acc);
            acc = fmaf(w1, g_h3[s1 * 16 + lane], acc);
            acc = fmaf(w2, g_h3[s2 * 16 + lane], acc);
            acc = fmaf(w3, g_h3[s3 * 16 + lane], acc);
        }
    }
    for (; j < end; j++) {
        int s = g_esrc[j];
        float w = g_ew2[j];
        if (active) acc = fmaf(w, g_h3[s * 16 + lane], acc);
    }

    int g = batch[gw];
    if (active) {
        acc = fmaf(acc, di, b3[lane]);
        atomicAdd(&g_psum[g * CCNT + lane], acc);
    }
    if (lane == 0) atomicAdd(&g_pcnt[g], 1.0f);
}

// ---------------- final: mean + log_softmax ----------------
__global__ void k_finalize(float* __restrict__ out) {
    int g = threadIdx.x;
    if (g >= GCNT) return;
    float c = fmaxf(g_pcnt[g], 1.0f);
    float v[CCNT];
    float m = -1e30f;
#pragma unroll
    for (int j = 0; j < CCNT; j++) {
        v[j] = g_psum[g * CCNT + j] / c;
        m = fmaxf(m, v[j]);
    }
    float s = 0.0f;
#pragma unroll
    for (int j = 0; j < CCNT; j++) s += expf(v[j] - m);
    float lse = logf(s) + m;
#pragma unroll
    for (int j = 0; j < CCNT; j++) out[g * CCNT + j] = v[j] - lse;
}

// ---------------- launch ----------------
extern "C" void kernel_launch(void* const* d_in, const int* in_sizes, int n_in,
                              void* d_out, int out_size) {
    const float* x    = (const float*)d_in[0];
    const int*   ei   = (const int*)d_in[1];
    const float* ea   = (const float*)d_in[2];
    const int*   bat  = (const int*)d_in[3];
    const float* W1   = (const float*)d_in[4];
    const float* b1   = (const float*)d_in[5];
    const float* W2   = (const float*)d_in[6];
    const float* b2   = (const float*)d_in[7];
    const float* W3   = (const float*)d_in[8];
    const float* b3   = (const float*)d_in[9];
    float* out = (float*)d_out;

    int n = in_sizes[0] / HDIM;   // 50000
    int e = in_sizes[1] / 2;      // 800000
    const int* src = ei;
    const int* dst = ei + e;

    unsigned* ghb;
    float* gagg;
    cudaGetSymbolAddress((void**)&ghb, g_hb);
    cudaGetSymbolAddress((void**)&gagg, g_agg);

    int nb = (n + SCAN_BLK - 1) / SCAN_BLK;
    int gemmBlocks = (n + 127) / 128;
    int aggBlocks = (n * 32 + 255) / 256;

    cudaStream_t s0 = (cudaStream_t)0;

    // fork a side stream: layer-1 GEMM is independent of CSR preprocessing
    cudaStream_t s2;
    cudaStreamCreateWithFlags(&s2, cudaStreamNonBlocking);
    cudaEvent_t evFork, evJoin;
    cudaEventCreateWithFlags(&evFork, cudaEventDisableTiming);
    cudaEventCreateWithFlags(&evJoin, cudaEventDisableTiming);

    cudaEventRecord(evFork, s0);
    cudaStreamWaitEvent(s2, evFork, 0);
    sgemm128_tf32<<<gemmBlocks, 256, 0, s2>>>(x, W1, ghb, n);   // h = x@W1 (bf16 packed)
    cudaEventRecord(evJoin, s2);

    // preprocessing on main stream (concurrent with the GEMM above)
    k_init<<<(n + 255) / 256, 256, 0, s0>>>(n);
    k_count<<<(e + 255) / 256, 256, 0, s0>>>(dst, ea, e);
    k_scan1<<<nb, SCAN_BLK, 0, s0>>>(n);
    k_scan2<<<1, 128, 0, s0>>>(nb, n, e);
    k_scan3<<<nb, SCAN_BLK, 0, s0>>>(n);
    k_scatter<<<(e + 255) / 256, 256, 0, s0>>>(src, dst, ea, e);

    // join: aggregation needs both CSR and h
    cudaStreamWaitEvent(s0, evJoin, 0);
    agg_h128<<<aggBlocks, 256, 0, s0>>>(ghb, gagg, b1, 1, n);

    // layer 2
    sgemm128_tf32<<<gemmBlocks, 256, 0, s0>>>(gagg, W2, ghb, n);
    agg_h128<<<aggBlocks, 256, 0, s0>>>(ghb, gagg, b2, 1, n);

    // layer 3: project to C first, then aggregate + pool
    gemm_w3<<<(n + 31) / 32, 512, 0, s0>>>(gagg, W3, n);
    agg_c16_pool<<<aggBlocks, 256, 0, s0>>>(bat, b3, n);

    k_finalize<<<1, 128, 0, s0>>>(out);
    // NOTE: s2/events intentionally not destroyed — kernel_launch is invoked
    // only for the correctness run and one graph capture.
}

// round 10
// speedup vs baseline: 1.4593x; 1.0114x over previous
#include <cuda_runtime.h>
#include <cuda_bf16.h>
#include <math.h>

// Problem constants
#define NMAX 50000
#define EMAX 800000
#define HDIM 128
#define GCNT 128
#define CCNT 10
#define SCAN_BLK 512

// ---------------- device scratch (no cudaMalloc allowed) ----------------
__device__ unsigned g_hb[NMAX * 64];    // h as packed bf16x2 (64 uint32 per row)
__device__ float g_agg[NMAX * HDIM];    // layer-1 agg output (fp32, GEMM2 input)
__device__ float g_h3[NMAX * 16];       // layer-3 projected features (padded C)
__device__ float g_deg[NMAX];
__device__ float g_dinv[NMAX];
__device__ int   g_cnt[NMAX];
__device__ int   g_row[NMAX + 1];
__device__ int   g_cur[NMAX];
__device__ int   g_bsum[128];
__device__ uint2 g_edge[EMAX];          // packed (src, bits(ew*dinv[src]))
__device__ float g_psum[GCNT * CCNT];
__device__ float g_pcnt[GCNT];

// ---------------- preprocessing ----------------

__global__ void k_init(int n) {
    int i = blockIdx.x * blockDim.x + threadIdx.x;
    if (i < n) { g_deg[i] = 1.0f; g_cnt[i] = 0; }
    if (i < GCNT * CCNT) g_psum[i] = 0.0f;
    if (i < GCNT) g_pcnt[i] = 0.0f;
}

__global__ void k_count(const int* __restrict__ dst, const float* __restrict__ ew, int e) {
    int i = blockIdx.x * blockDim.x + threadIdx.x;
    if (i >= e) return;
    int d = dst[i];
    atomicAdd(&g_deg[d], ew[i]);
    atomicAdd(&g_cnt[d], 1);
}

__global__ void k_scan1(int n) {
    __shared__ int sd[SCAN_BLK];
    int tid = threadIdx.x;
    int i = blockIdx.x * SCAN_BLK + tid;
    int v = (i < n) ? g_cnt[i] : 0;
    sd[tid] = v;
    __syncthreads();
#pragma unroll
    for (int off = 1; off < SCAN_BLK; off <<= 1) {
        int t = (tid >= off) ? sd[tid - off] : 0;
        __syncthreads();
        sd[tid] += t;
        __syncthreads();
    }
    if (i < n) g_row[i] = sd[tid] - v;
    if (tid == SCAN_BLK - 1) g_bsum[blockIdx.x] = sd[SCAN_BLK - 1];
}

// scan3 with scan2 folded in: each block sums the preceding block-sums itself.
__global__ void k_scan3(int n, int e, int nb) {
    __shared__ int sb[128];
    int tid = threadIdx.x;
    if (tid < 128) sb[tid] = (tid < nb) ? g_bsum[tid] : 0;
    __syncthreads();
    int b = blockIdx.x;
    int off = 0;
    for (int k = 0; k < b; k++) off += sb[k];   // smem broadcast reads, cheap
    int i = b * SCAN_BLK + tid;
    if (i < n) {
        int r = g_row[i] + off;
        g_row[i] = r;
        g_cur[i] = r;
        float d = g_deg[i];
        g_dinv[i] = (d > 0.0f) ? rsqrtf(d) : 0.0f;
    }
    if (b == 0 && tid == 0) g_row[n] = e;
}

__global__ void k_scatter(const int* __restrict__ src, const int* __restrict__ dst,
                          const float* __restrict__ ew, int e) {
    int i = blockIdx.x * blockDim.x + threadIdx.x;
    if (i >= e) return;
    int s = src[i], d = dst[i];
    int pos = atomicAdd(&g_cur[d], 1);
    g_edge[pos] = make_uint2((unsigned)s, __float_as_uint(ew[i] * g_dinv[s]));
}

// ---------------- tensor-core GEMM (3xTF32): [M,128] @ [128,128] -> bf16x2 ----
#define TF32_MASK 0xFFFFE000u

__device__ __forceinline__ void mma_tf32(float* c, const unsigned* a,
                                         unsigned b0, unsigned b1) {
    asm volatile(
        "mma.sync.aligned.m16n8k8.row.col.f32.tf32.tf32.f32 "
        "{%0,%1,%2,%3}, {%4,%5,%6,%7}, {%8,%9}, {%0,%1,%2,%3};\n"
        : "+f"(c[0]), "+f"(c[1]), "+f"(c[2]), "+f"(c[3])
        : "r"(a[0]), "r"(a[1]), "r"(a[2]), "r"(a[3]), "r"(b0), "r"(b1));
}

__global__ __launch_bounds__(256, 2)
void sgemm128_tf32(const float* __restrict__ A, const float* __restrict__ B,
                   unsigned* __restrict__ Cb, int M) {
    __shared__ float As[2][128][20];
    __shared__ float Bs[2][16][136];

    int tid  = threadIdx.x;
    int warp = tid >> 5;
    int lane = tid & 31;
    int g = lane >> 2;
    int t = lane & 3;
    int r0 = warp * 16;
    int rowBase = blockIdx.x * 128;

    int aRow = tid >> 1;
    int aOff = (tid & 1) * 8;
    int bRow = tid >> 4;
    int bOff = (tid & 15) * 8;

    bool aOk = (rowBase + aRow) < M;
    const float* Ap = A + (size_t)(aOk ? rowBase + aRow : 0) * 128;

    float acc[16][4];
#pragma unroll
    for (int j = 0; j < 16; j++)
#pragma unroll
        for (int q = 0; q < 4; q++) acc[j][q] = 0.0f;

    {
        float4 z = make_float4(0.f, 0.f, 0.f, 0.f);
        float4 a0 = aOk ? *(const float4*)(Ap + aOff)     : z;
        float4 a1 = aOk ? *(const float4*)(Ap + aOff + 4) : z;
        *(float4*)&As[0][aRow][aOff]     = a0;
        *(float4*)&As[0][aRow][aOff + 4] = a1;
        float4 b0 = *(const float4*)(B + (size_t)bRow * 128 + bOff);
        float4 b1 = *(const float4*)(B + (size_t)bRow * 128 + bOff + 4);
        *(float4*)&Bs[0][bRow][bOff]     = b0;
        *(float4*)&Bs[0][bRow][bOff + 4] = b1;
    }
    __syncthreads();

    int p = 0;
    for (int k0 = 0; k0 < 128; k0 += 16) {
        bool more = (k0 + 16) < 128;
        float4 pa0, pa1, pb0, pb1;
        if (more) {
            float4 z = make_float4(0.f, 0.f, 0.f, 0.f);
            pa0 = aOk ? *(const float4*)(Ap + k0 + 16 + aOff)     : z;
            pa1 = aOk ? *(const float4*)(Ap + k0 + 16 + aOff + 4) : z;
            pb0 = *(const float4*)(B + (size_t)(k0 + 16 + bRow) * 128 + bOff);
            pb1 = *(const float4*)(B + (size_t)(k0 + 16 + bRow) * 128 + bOff + 4);
        }

#pragma unroll
        for (int kk = 0; kk < 16; kk += 8) {
            float av0 = As[p][r0 + g    ][kk + t];
            float av1 = As[p][r0 + g + 8][kk + t];
            float av2 = As[p][r0 + g    ][kk + t + 4];
            float av3 = As[p][r0 + g + 8][kk + t + 4];
            unsigned ahi[4], alo[4];
            {
                float av[4] = {av0, av1, av2, av3};
#pragma unroll
                for (int q = 0; q < 4; q++) {
                    unsigned h = __float_as_uint(av[q]) & TF32_MASK;
                    ahi[q] = h;
                    alo[q] = __float_as_uint(av[q] - __uint_as_float(h));
                }
            }
#pragma unroll
            for (int j = 0; j < 16; j++) {
                float bv0 = Bs[p][kk + t    ][j * 8 + g];
                float bv1 = Bs[p][kk + t + 4][j * 8 + g];
                unsigned bh0 = __float_as_uint(bv0) & TF32_MASK;
                unsigned bh1 = __float_as_uint(bv1) & TF32_MASK;
                unsigned bl0 = __float_as_uint(bv0 - __uint_as_float(bh0));
                unsigned bl1 = __float_as_uint(bv1 - __uint_as_float(bh1));
                mma_tf32(acc[j], ahi, bh0, bh1);
                mma_tf32(acc[j], ahi, bl0, bl1);
                mma_tf32(acc[j], alo, bh0, bh1);
            }
        }

        if (more) {
            int q = p ^ 1;
            *(float4*)&As[q][aRow][aOff]     = pa0;
            *(float4*)&As[q][aRow][aOff + 4] = pa1;
            *(float4*)&Bs[q][bRow][bOff]     = pb0;
            *(float4*)&Bs[q][bRow][bOff + 4] = pb1;
            __syncthreads();
            p = q;
        }
    }

    int rA = rowBase + r0 + g;
    int rB = rA + 8;
#pragma unroll
    for (int j = 0; j < 16; j++) {
        int widx = j * 4 + t;
        if (rA < M) {
            __nv_bfloat162 v = __float22bfloat162_rn(make_float2(acc[j][0], acc[j][1]));
            Cb[(size_t)rA * 64 + widx] = *(unsigned*)&v;
        }
        if (rB < M) {
            __nv_bfloat162 v = __float22bfloat162_rn(make_float2(acc[j][2], acc[j][3]));
            Cb[(size_t)rB * 64 + widx] = *(unsigned*)&v;
        }
    }
}

// ---------------- shared gather body (bf16 in, fp32 acc) ----------------
__device__ __forceinline__ float4 gather_node(const uint2* __restrict__ h2,
                                              int gw, int lane, float di) {
    float4 acc;
    {
        uint2 u = h2[(size_t)gw * 32 + lane];
        float2 f0 = __bfloat1622float2(*(const __nv_bfloat162*)&u.x);
        float2 f1 = __bfloat1622float2(*(const __nv_bfloat162*)&u.y);
        acc.x = f0.x * di; acc.y = f0.y * di;
        acc.z = f1.x * di; acc.w = f1.y * di;
    }
    int j = g_row[gw];
    int end = g_row[gw + 1];
    for (; j + 4 <= end; j += 4) {
        uint2 e0 = g_edge[j], e1 = g_edge[j + 1], e2 = g_edge[j + 2], e3 = g_edge[j + 3];
        float w0 = __uint_as_float(e0.y), w1 = __uint_as_float(e1.y);
        float w2 = __uint_as_float(e2.y), w3 = __uint_as_float(e3.y);
        uint2 u0 = h2[(size_t)e0.x * 32 + lane];
        uint2 u1 = h2[(size_t)e1.x * 32 + lane];
        uint2 u2 = h2[(size_t)e2.x * 32 + lane];
        uint2 u3 = h2[(size_t)e3.x * 32 + lane];
        float2 a0 = __bfloat1622float2(*(const __nv_bfloat162*)&u0.x);
        float2 b0 = __bfloat1622float2(*(const __nv_bfloat162*)&u0.y);
        float2 a1 = __bfloat1622float2(*(const __nv_bfloat162*)&u1.x);
        float2 b1 = __bfloat1622float2(*(const __nv_bfloat162*)&u1.y);
        float2 a2 = __bfloat1622float2(*(const __nv_bfloat162*)&u2.x);
        float2 b2 = __bfloat1622float2(*(const __nv_bfloat162*)&u2.y);
        float2 a3 = __bfloat1622float2(*(const __nv_bfloat162*)&u3.x);
        float2 b3 = __bfloat1622float2(*(const __nv_bfloat162*)&u3.y);
        acc.x = fmaf(w0, a0.x, acc.x); acc.y = fmaf(w0, a0.y, acc.y);
        acc.z = fmaf(w0, b0.x, acc.z); acc.w = fmaf(w0, b0.y, acc.w);
        acc.x = fmaf(w1, a1.x, acc.x); acc.y = fmaf(w1, a1.y, acc.y);
        acc.z = fmaf(w1, b1.x, acc.z); acc.w = fmaf(w1, b1.y, acc.w);
        acc.x = fmaf(w2, a2.x, acc.x); acc.y = fmaf(w2, a2.y, acc.y);
        acc.z = fmaf(w2, b2.x, acc.z); acc.w = fmaf(w2, b2.y, acc.w);
        acc.x = fmaf(w3, a3.x, acc.x); acc.y = fmaf(w3, a3.y, acc.y);
        acc.z = fmaf(w3, b3.x, acc.z); acc.w = fmaf(w3, b3.y, acc.w);
    }
    for (; j < end; j++) {
        uint2 ed = g_edge[j];
        float w = __uint_as_float(ed.y);
        uint2 u = h2[(size_t)ed.x * 32 + lane];
        float2 f0 = __bfloat1622float2(*(const __nv_bfloat162*)&u.x);
        float2 f1 = __bfloat1622float2(*(const __nv_bfloat162*)&u.y);
        acc.x = fmaf(w, f0.x, acc.x); acc.y = fmaf(w, f0.y, acc.y);
        acc.z = fmaf(w, f1.x, acc.z); acc.w = fmaf(w, f1.y, acc.w);
    }
    return acc;
}

// ---------------- layer-1 aggregation: out fp32 (GEMM2 input) ----------------
__global__ __launch_bounds__(256)
void agg_h128(const unsigned* __restrict__ hb, float* __restrict__ out,
              const float* __restrict__ bias, int n) {
    int gw = (blockIdx.x * blockDim.x + threadIdx.x) >> 5;
    if (gw >= n) return;
    int lane = threadIdx.x & 31;
    float di = g_dinv[gw];
    float4 acc = gather_node((const uint2*)hb, gw, lane, di);

    float4 bb = ((const float4*)bias)[lane];
    acc.x = fmaxf(fmaf(acc.x, di, bb.x), 0.f);
    acc.y = fmaxf(fmaf(acc.y, di, bb.y), 0.f);
    acc.z = fmaxf(fmaf(acc.z, di, bb.z), 0.f);
    acc.w = fmaxf(fmaf(acc.w, di, bb.w), 0.f);
    ((float4*)out)[(size_t)gw * 32 + lane] = acc;
}

// ---------------- layer-2 aggregation + fused W3 projection ----------------
// h3[node][c] = sum_k relu(agg2+b2)[k] * W3[k][c]; W3 staged c-major in smem.
__global__ __launch_bounds__(512)
void agg_h128_w3(const unsigned* __restrict__ hb, const float* __restrict__ bias,
                 const float* __restrict__ W3, int n) {
    __shared__ float Wsc[CCNT][HDIM];   // c-major: row c = W3[:,c]
    for (int idx = threadIdx.x; idx < HDIM * CCNT; idx += 512) {
        int k = idx / CCNT, c = idx % CCNT;
        Wsc[c][k] = W3[idx];
    }
    __syncthreads();

    int gw = (blockIdx.x * blockDim.x + threadIdx.x) >> 5;
    if (gw >= n) return;
    int lane = threadIdx.x & 31;
    float di = g_dinv[gw];
    float4 acc = gather_node((const uint2*)hb, gw, lane, di);

    float4 bb = ((const float4*)bias)[lane];
    acc.x = fmaxf(fmaf(acc.x, di, bb.x), 0.f);
    acc.y = fmaxf(fmaf(acc.y, di, bb.y), 0.f);
    acc.z = fmaxf(fmaf(acc.z, di, bb.z), 0.f);
    acc.w = fmaxf(fmaf(acc.w, di, bb.w), 0.f);

    // project: p[c] = dot(acc, W3[4l..4l+3][c]); reduce over lanes
    float p[CCNT];
#pragma unroll
    for (int c = 0; c < CCNT; c++) {
        float4 w = *(const float4*)&Wsc[c][4 * lane];
        p[c] = acc.x * w.x + acc.y * w.y + acc.z * w.z + acc.w * w.w;
    }
#pragma unroll
    for (int c = 0; c < CCNT; c++) {
#pragma unroll
        for (int off = 16; off > 0; off >>= 1)
            p[c] += __shfl_xor_sync(0xffffffffu, p[c], off);
    }
    if (lane == 0) {
        float* dst = &g_h3[(size_t)gw * 16];
#pragma unroll
        for (int c = 0; c < CCNT; c++) dst[c] = p[c];
    }
}

// ---------------- layer 3 aggregation + pool ----------------
__global__ __launch_bounds__(256)
void agg_c16_pool(const int* __restrict__ batch, const float* __restrict__ b3, int n) {
    int gw = (blockIdx.x * blockDim.x + threadIdx.x) >> 5;
    if (gw >= n) return;
    int lane = threadIdx.x & 31;
    bool active = (lane < CCNT);

    float di = g_dinv[gw];
    float acc = 0.0f;
    if (active) acc = g_h3[gw * 16 + lane] * di;

    int j = g_row[gw];
    int end = g_row[gw + 1];
    for (; j + 4 <= end; j += 4) {
        uint2 e0 = g_edge[j], e1 = g_edge[j + 1], e2 = g_edge[j + 2], e3 = g_edge[j + 3];
        if (active) {
            acc = fmaf(__uint_as_float(e0.y), g_h3[(size_t)e0.x * 16 + lane], acc);
            acc = fmaf(__uint_as_float(e1.y), g_h3[(size_t)e1.x * 16 + lane], acc);
            acc = fmaf(__uint_as_float(e2.y), g_h3[(size_t)e2.x * 16 + lane], acc);
            acc = fmaf(__uint_as_float(e3.y), g_h3[(size_t)e3.x * 16 + lane], acc);
        }
    }
    for (; j < end; j++) {
        uint2 ed = g_edge[j];
        if (active) acc = fmaf(__uint_as_float(ed.y), g_h3[(size_t)ed.x * 16 + lane], acc);
    }

    int g = batch[gw];
    if (active) {
        acc = fmaf(acc, di, b3[lane]);
        atomicAdd(&g_psum[g * CCNT + lane], acc);
    }
    if (lane == 0) atomicAdd(&g_pcnt[g], 1.0f);
}

// ---------------- final: mean + log_softmax ----------------
__global__ void k_finalize(float* __restrict__ out) {
    int g = threadIdx.x;
    if (g >= GCNT) return;
    float c = fmaxf(g_pcnt[g], 1.0f);
    float v[CCNT];
    float m = -1e30f;
#pragma unroll
    for (int j = 0; j < CCNT; j++) {
        v[j] = g_psum[g * CCNT + j] / c;
        m = fmaxf(m, v[j]);
    }
    float s = 0.0f;
#pragma unroll
    for (int j = 0; j < CCNT; j++) s += expf(v[j] - m);
    float lse = logf(s) + m;
#pragma unroll
    for (int j = 0; j < CCNT; j++) out[g * CCNT + j] = v[j] - lse;
}

// ---------------- launch ----------------
extern "C" void kernel_launch(void* const* d_in, const int* in_sizes, int n_in,
                              void* d_out, int out_size) {
    const float* x    = (const float*)d_in[0];
    const int*   ei   = (const int*)d_in[1];
    const float* ea   = (const float*)d_in[2];
    const int*   bat  = (const int*)d_in[3];
    const float* W1   = (const float*)d_in[4];
    const float* b1   = (const float*)d_in[5];
    const float* W2   = (const float*)d_in[6];
    const float* b2   = (const float*)d_in[7];
    const float* W3   = (const float*)d_in[8];
    const float* b3   = (const float*)d_in[9];
    float* out = (float*)d_out;

    int n = in_sizes[0] / HDIM;   // 50000
    int e = in_sizes[1] / 2;      // 800000
    const int* src = ei;
    const int* dst = ei + e;

    unsigned* ghb;
    float* gagg;
    cudaGetSymbolAddress((void**)&ghb, g_hb);
    cudaGetSymbolAddress((void**)&gagg, g_agg);

    int nb = (n + SCAN_BLK - 1) / SCAN_BLK;
    int gemmBlocks = (n + 127) / 128;
    int aggBlocks256 = (n * 32 + 255) / 256;
    int aggBlocks512 = (n * 32 + 511) / 512;

    cudaStream_t s0 = (cudaStream_t)0;

    // fork a side stream: layer-1 GEMM is independent of CSR preprocessing
    cudaStream_t s2;
    cudaStreamCreateWithFlags(&s2, cudaStreamNonBlocking);
    cudaEvent_t evFork, evJoin;
    cudaEventCreateWithFlags(&evFork, cudaEventDisableTiming);
    cudaEventCreateWithFlags(&evJoin, cudaEventDisableTiming);

    cudaEventRecord(evFork, s0);
    cudaStreamWaitEvent(s2, evFork, 0);
    sgemm128_tf32<<<gemmBlocks, 256, 0, s2>>>(x, W1, ghb, n);   // h = x@W1 (bf16 packed)
    cudaEventRecord(evJoin, s2);

    // preprocessing on main stream (concurrent with the GEMM above)
    k_init<<<(n + 255) / 256, 256, 0, s0>>>(n);
    k_count<<<(e + 255) / 256, 256, 0, s0>>>(dst, ea, e);
    k_scan1<<<nb, SCAN_BLK, 0, s0>>>(n);
    k_scan3<<<nb, SCAN_BLK, 0, s0>>>(n, e, nb);
    k_scatter<<<(e + 255) / 256, 256, 0, s0>>>(src, dst, ea, e);

    // join: aggregation needs both CSR and h
    cudaStreamWaitEvent(s0, evJoin, 0);
    agg_h128<<<aggBlocks256, 256, 0, s0>>>(ghb, gagg, b1, n);

    // layer 2 + fused W3 projection
    sgemm128_tf32<<<gemmBlocks, 256, 0, s0>>>(gagg, W2, ghb, n);
    agg_h128_w3<<<aggBlocks512, 512, 0, s0>>>(ghb, b2, W3, n);

    // layer 3 aggregation + pool, then finalize
    agg_c16_pool<<<aggBlocks256, 256, 0, s0>>>(bat, b3, n);
    k_finalize<<<1, 128, 0, s0>>>(out);
    // NOTE: s2/events intentionally not destroyed — kernel_launch is invoked
    // only for the correctness run and one graph capture.
}

// round 11
// speedup vs baseline: 1.6579x; 1.1361x over previous
#include <cuda_runtime.h>
#include <cuda_bf16.h>
#include <math.h>

// Problem constants
#define NMAX 50000
#define EMAX 800000
#define HDIM 128
#define GCNT 128
#define CCNT 10
#define SCAN_BLK 512

// ---------------- device scratch (no cudaMalloc allowed) ----------------
__device__ unsigned g_hb[NMAX * 64];    // h as packed bf16x2 (64 uint32 per row)
__device__ float g_agg[NMAX * HDIM];    // layer-1 agg output (fp32, GEMM2 input)
__device__ float g_h3[NMAX * 16];       // layer-3 projected features (padded C)
__device__ float g_deg[NMAX];
__device__ float g_dinv[NMAX];
__device__ int   g_cnt[NMAX];
__device__ int   g_row[NMAX + 1];
__device__ int   g_cur[NMAX];
__device__ int   g_bsum[128];
__device__ uint2 g_edge[EMAX];          // packed (src, bits(ew*dinv[src]))
__device__ float g_psum[GCNT * CCNT];
__device__ float g_pcnt[GCNT];

// ---------------- preprocessing ----------------

__global__ void k_init(int n) {
    int i = blockIdx.x * blockDim.x + threadIdx.x;
    if (i < n) { g_deg[i] = 1.0f; g_cnt[i] = 0; }
    if (i < GCNT * CCNT) g_psum[i] = 0.0f;
    if (i < GCNT) g_pcnt[i] = 0.0f;
}

__global__ void k_count(const int* __restrict__ dst, const float* __restrict__ ew, int e) {
    int i = blockIdx.x * blockDim.x + threadIdx.x;
    if (i >= e) return;
    int d = dst[i];
    atomicAdd(&g_deg[d], ew[i]);
    atomicAdd(&g_cnt[d], 1);
}

__global__ void k_scan1(int n) {
    __shared__ int sd[SCAN_BLK];
    int tid = threadIdx.x;
    int i = blockIdx.x * SCAN_BLK + tid;
    int v = (i < n) ? g_cnt[i] : 0;
    sd[tid] = v;
    __syncthreads();
#pragma unroll
    for (int off = 1; off < SCAN_BLK; off <<= 1) {
        int t = (tid >= off) ? sd[tid - off] : 0;
        __syncthreads();
        sd[tid] += t;
        __syncthreads();
    }
    if (i < n) g_row[i] = sd[tid] - v;
    if (tid == SCAN_BLK - 1) g_bsum[blockIdx.x] = sd[SCAN_BLK - 1];
}

// scan3 with scan2 folded in: each block sums the preceding block-sums itself.
__global__ void k_scan3(int n, int e, int nb) {
    __shared__ int sb[128];
    int tid = threadIdx.x;
    if (tid < 128) sb[tid] = (tid < nb) ? g_bsum[tid] : 0;
    __syncthreads();
    int b = blockIdx.x;
    int off = 0;
    for (int k = 0; k < b; k++) off += sb[k];
    int i = b * SCAN_BLK + tid;
    if (i < n) {
        int r = g_row[i] + off;
        g_row[i] = r;
        g_cur[i] = r;
        float d = g_deg[i];
        g_dinv[i] = (d > 0.0f) ? rsqrtf(d) : 0.0f;
    }
    if (b == 0 && tid == 0) g_row[n] = e;
}

__global__ void k_scatter(const int* __restrict__ src, const int* __restrict__ dst,
                          const float* __restrict__ ew, int e) {
    int i = blockIdx.x * blockDim.x + threadIdx.x;
    if (i >= e) return;
    int s = src[i], d = dst[i];
    int pos = atomicAdd(&g_cur[d], 1);
    g_edge[pos] = make_uint2((unsigned)s, __float_as_uint(ew[i] * g_dinv[s]));
}

// ---------------- tensor-core GEMM (single tf32, cvt-at-load): ----------------
// [M,128] @ [128,128] -> bf16x2. Operands rounded to tf32 (rna) at smem store;
// inner loop is pure LDS + one HMMA per (kk, j). Same proven R3 layout/banks.
__device__ __forceinline__ void mma_tf32(float* c, const unsigned* a,
                                         unsigned b0, unsigned b1) {
    asm volatile(
        "mma.sync.aligned.m16n8k8.row.col.f32.tf32.tf32.f32 "
        "{%0,%1,%2,%3}, {%4,%5,%6,%7}, {%8,%9}, {%0,%1,%2,%3};\n"
        : "+f"(c[0]), "+f"(c[1]), "+f"(c[2]), "+f"(c[3])
        : "r"(a[0]), "r"(a[1]), "r"(a[2]), "r"(a[3]), "r"(b0), "r"(b1));
}

__device__ __forceinline__ float to_tf32(float v) {
    // round-to-nearest tf32 (unbiased — truncation bias would accumulate over K)
    float r;
    asm("cvt.rna.tf32.f32 %0, %1;" : "=f"(r) : "f"(v));
    return r;
}

__global__ __launch_bounds__(256, 2)
void sgemm128_tf32(const float* __restrict__ A, const float* __restrict__ B,
                   unsigned* __restrict__ Cb, int M) {
    __shared__ float As[2][128][20];
    __shared__ float Bs[2][16][136];

    int tid  = threadIdx.x;
    int warp = tid >> 5;
    int lane = tid & 31;
    int g = lane >> 2;
    int t = lane & 3;
    int r0 = warp * 16;
    int rowBase = blockIdx.x * 128;

    int aRow = tid >> 1;
    int aOff = (tid & 1) * 8;
    int bRow = tid >> 4;
    int bOff = (tid & 15) * 8;

    bool aOk = (rowBase + aRow) < M;
    const float* Ap = A + (size_t)(aOk ? rowBase + aRow : 0) * 128;

    float acc[16][4];
#pragma unroll
    for (int j = 0; j < 16; j++)
#pragma unroll
        for (int q = 0; q < 4; q++) acc[j][q] = 0.0f;

    // preload stage 0 (tf32-rounded)
    {
        float4 z = make_float4(0.f, 0.f, 0.f, 0.f);
        float4 a0 = aOk ? *(const float4*)(Ap + aOff)     : z;
        float4 a1 = aOk ? *(const float4*)(Ap + aOff + 4) : z;
        a0.x = to_tf32(a0.x); a0.y = to_tf32(a0.y); a0.z = to_tf32(a0.z); a0.w = to_tf32(a0.w);
        a1.x = to_tf32(a1.x); a1.y = to_tf32(a1.y); a1.z = to_tf32(a1.z); a1.w = to_tf32(a1.w);
        *(float4*)&As[0][aRow][aOff]     = a0;
        *(float4*)&As[0][aRow][aOff + 4] = a1;
        float4 b0 = *(const float4*)(B + (size_t)bRow * 128 + bOff);
        float4 b1 = *(const float4*)(B + (size_t)bRow * 128 + bOff + 4);
        b0.x = to_tf32(b0.x); b0.y = to_tf32(b0.y); b0.z = to_tf32(b0.z); b0.w = to_tf32(b0.w);
        b1.x = to_tf32(b1.x); b1.y = to_tf32(b1.y); b1.z = to_tf32(b1.z); b1.w = to_tf32(b1.w);
        *(float4*)&Bs[0][bRow][bOff]     = b0;
        *(float4*)&Bs[0][bRow][bOff + 4] = b1;
    }
    __syncthreads();

    int p = 0;
    for (int k0 = 0; k0 < 128; k0 += 16) {
        bool more = (k0 + 16) < 128;
        float4 pa0, pa1, pb0, pb1;
        if (more) {
            float4 z = make_float4(0.f, 0.f, 0.f, 0.f);
            pa0 = aOk ? *(const float4*)(Ap + k0 + 16 + aOff)     : z;
            pa1 = aOk ? *(const float4*)(Ap + k0 + 16 + aOff + 4) : z;
            pb0 = *(const float4*)(B + (size_t)(k0 + 16 + bRow) * 128 + bOff);
            pb1 = *(const float4*)(B + (size_t)(k0 + 16 + bRow) * 128 + bOff + 4);
        }

#pragma unroll
        for (int kk = 0; kk < 16; kk += 8) {
            unsigned a[4];
            a[0] = __float_as_uint(As[p][r0 + g    ][kk + t]);
            a[1] = __float_as_uint(As[p][r0 + g + 8][kk + t]);
            a[2] = __float_as_uint(As[p][r0 + g    ][kk + t + 4]);
            a[3] = __float_as_uint(As[p][r0 + g + 8][kk + t + 4]);
#pragma unroll
            for (int j = 0; j < 16; j++) {
                unsigned b0 = __float_as_uint(Bs[p][kk + t    ][j * 8 + g]);
                unsigned b1 = __float_as_uint(Bs[p][kk + t + 4][j * 8 + g]);
                mma_tf32(acc[j], a, b0, b1);
            }
        }

        if (more) {
            pa0.x = to_tf32(pa0.x); pa0.y = to_tf32(pa0.y); pa0.z = to_tf32(pa0.z); pa0.w = to_tf32(pa0.w);
            pa1.x = to_tf32(pa1.x); pa1.y = to_tf32(pa1.y); pa1.z = to_tf32(pa1.z); pa1.w = to_tf32(pa1.w);
            pb0.x = to_tf32(pb0.x); pb0.y = to_tf32(pb0.y); pb0.z = to_tf32(pb0.z); pb0.w = to_tf32(pb0.w);
            pb1.x = to_tf32(pb1.x); pb1.y = to_tf32(pb1.y); pb1.z = to_tf32(pb1.z); pb1.w = to_tf32(pb1.w);
            int q = p ^ 1;
            *(float4*)&As[q][aRow][aOff]     = pa0;
            *(float4*)&As[q][aRow][aOff + 4] = pa1;
            *(float4*)&Bs[q][bRow][bOff]     = pb0;
            *(float4*)&Bs[q][bRow][bOff + 4] = pb1;
            __syncthreads();
            p = q;
        }
    }

    int rA = rowBase + r0 + g;
    int rB = rA + 8;
#pragma unroll
    for (int j = 0; j < 16; j++) {
        int widx = j * 4 + t;
        if (rA < M) {
            __nv_bfloat162 v = __float22bfloat162_rn(make_float2(acc[j][0], acc[j][1]));
            Cb[(size_t)rA * 64 + widx] = *(unsigned*)&v;
        }
        if (rB < M) {
            __nv_bfloat162 v = __float22bfloat162_rn(make_float2(acc[j][2], acc[j][3]));
            Cb[(size_t)rB * 64 + widx] = *(unsigned*)&v;
        }
    }
}

// ---------------- shared gather body (bf16 in, fp32 acc) ----------------
__device__ __forceinline__ float4 gather_node(const uint2* __restrict__ h2,
                                              int gw, int lane, float di) {
    float4 acc;
    {
        uint2 u = h2[(size_t)gw * 32 + lane];
        float2 f0 = __bfloat1622float2(*(const __nv_bfloat162*)&u.x);
        float2 f1 = __bfloat1622float2(*(const __nv_bfloat162*)&u.y);
        acc.x = f0.x * di; acc.y = f0.y * di;
        acc.z = f1.x * di; acc.w = f1.y * di;
    }
    int j = g_row[gw];
    int end = g_row[gw + 1];
    for (; j + 4 <= end; j += 4) {
        uint2 e0 = g_edge[j], e1 = g_edge[j + 1], e2 = g_edge[j + 2], e3 = g_edge[j + 3];
        float w0 = __uint_as_float(e0.y), w1 = __uint_as_float(e1.y);
        float w2 = __uint_as_float(e2.y), w3 = __uint_as_float(e3.y);
        uint2 u0 = h2[(size_t)e0.x * 32 + lane];
        uint2 u1 = h2[(size_t)e1.x * 32 + lane];
        uint2 u2 = h2[(size_t)e2.x * 32 + lane];
        uint2 u3 = h2[(size_t)e3.x * 32 + lane];
        float2 a0 = __bfloat1622float2(*(const __nv_bfloat162*)&u0.x);
        float2 b0 = __bfloat1622float2(*(const __nv_bfloat162*)&u0.y);
        float2 a1 = __bfloat1622float2(*(const __nv_bfloat162*)&u1.x);
        float2 b1 = __bfloat1622float2(*(const __nv_bfloat162*)&u1.y);
        float2 a2 = __bfloat1622float2(*(const __nv_bfloat162*)&u2.x);
        float2 b2 = __bfloat1622float2(*(const __nv_bfloat162*)&u2.y);
        float2 a3 = __bfloat1622float2(*(const __nv_bfloat162*)&u3.x);
        float2 b3 = __bfloat1622float2(*(const __nv_bfloat162*)&u3.y);
        acc.x = fmaf(w0, a0.x, acc.x); acc.y = fmaf(w0, a0.y, acc.y);
        acc.z = fmaf(w0, b0.x, acc.z); acc.w = fmaf(w0, b0.y, acc.w);
        acc.x = fmaf(w1, a1.x, acc.x); acc.y = fmaf(w1, a1.y, acc.y);
        acc.z = fmaf(w1, b1.x, acc.z); acc.w = fmaf(w1, b1.y, acc.w);
        acc.x = fmaf(w2, a2.x, acc.x); acc.y = fmaf(w2, a2.y, acc.y);
        acc.z = fmaf(w2, b2.x, acc.z); acc.w = fmaf(w2, b2.y, acc.w);
        acc.x = fmaf(w3, a3.x, acc.x); acc.y = fmaf(w3, a3.y, acc.y);
        acc.z = fmaf(w3, b3.x, acc.z); acc.w = fmaf(w3, b3.y, acc.w);
    }
    for (; j < end; j++) {
        uint2 ed = g_edge[j];
        float w = __uint_as_float(ed.y);
        uint2 u = h2[(size_t)ed.x * 32 + lane];
        float2 f0 = __bfloat1622float2(*(const __nv_bfloat162*)&u.x);
        float2 f1 = __bfloat1622float2(*(const __nv_bfloat162*)&u.y);
        acc.x = fmaf(w, f0.x, acc.x); acc.y = fmaf(w, f0.y, acc.y);
        acc.z = fmaf(w, f1.x, acc.z); acc.w = fmaf(w, f1.y, acc.w);
    }
    return acc;
}

// ---------------- layer-1 aggregation: out fp32 (GEMM2 input) ----------------
__global__ __launch_bounds__(256)
void agg_h128(const unsigned* __restrict__ hb, float* __restrict__ out,
              const float* __restrict__ bias, int n) {
    int gw = (blockIdx.x * blockDim.x + threadIdx.x) >> 5;
    if (gw >= n) return;
    int lane = threadIdx.x & 31;
    float di = g_dinv[gw];
    float4 acc = gather_node((const uint2*)hb, gw, lane, di);

    float4 bb = ((const float4*)bias)[lane];
    acc.x = fmaxf(fmaf(acc.x, di, bb.x), 0.f);
    acc.y = fmaxf(fmaf(acc.y, di, bb.y), 0.f);
    acc.z = fmaxf(fmaf(acc.z, di, bb.z), 0.f);
    acc.w = fmaxf(fmaf(acc.w, di, bb.w), 0.f);
    ((float4*)out)[(size_t)gw * 32 + lane] = acc;
}

// ---------------- layer-2 aggregation + fused W3 projection ----------------
__global__ __launch_bounds__(512)
void agg_h128_w3(const unsigned* __restrict__ hb, const float* __restrict__ bias,
                 const float* __restrict__ W3, int n) {
    __shared__ float Wsc[CCNT][HDIM];
    for (int idx = threadIdx.x; idx < HDIM * CCNT; idx += 512) {
        int k = idx / CCNT, c = idx % CCNT;
        Wsc[c][k] = W3[idx];
    }
    __syncthreads();

    int gw = (blockIdx.x * blockDim.x + threadIdx.x) >> 5;
    if (gw >= n) return;
    int lane = threadIdx.x & 31;
    float di = g_dinv[gw];
    float4 acc = gather_node((const uint2*)hb, gw, lane, di);

    float4 bb = ((const float4*)bias)[lane];
    acc.x = fmaxf(fmaf(acc.x, di, bb.x), 0.f);
    acc.y = fmaxf(fmaf(acc.y, di, bb.y), 0.f);
    acc.z = fmaxf(fmaf(acc.z, di, bb.z), 0.f);
    acc.w = fmaxf(fmaf(acc.w, di, bb.w), 0.f);

    float p[CCNT];
#pragma unroll
    for (int c = 0; c < CCNT; c++) {
        float4 w = *(const float4*)&Wsc[c][4 * lane];
        p[c] = acc.x * w.x + acc.y * w.y + acc.z * w.z + acc.w * w.w;
    }
#pragma unroll
    for (int c = 0; c < CCNT; c++) {
#pragma unroll
        for (int off = 16; off > 0; off >>= 1)
            p[c] += __shfl_xor_sync(0xffffffffu, p[c], off);
    }
    if (lane == 0) {
        float* dst = &g_h3[(size_t)gw * 16];
#pragma unroll
        for (int c = 0; c < CCNT; c++) dst[c] = p[c];
    }
}

// ---------------- layer 3 aggregation + pool ----------------
__global__ __launch_bounds__(256)
void agg_c16_pool(const int* __restrict__ batch, const float* __restrict__ b3, int n) {
    int gw = (blockIdx.x * blockDim.x + threadIdx.x) >> 5;
    if (gw >= n) return;
    int lane = threadIdx.x & 31;
    bool active = (lane < CCNT);

    float di = g_dinv[gw];
    float acc = 0.0f;
    if (active) acc = g_h3[gw * 16 + lane] * di;

    int j = g_row[gw];
    int end = g_row[gw + 1];
    for (; j + 4 <= end; j += 4) {
        uint2 e0 = g_edge[j], e1 = g_edge[j + 1], e2 = g_edge[j + 2], e3 = g_edge[j + 3];
        if (active) {
            acc = fmaf(__uint_as_float(e0.y), g_h3[(size_t)e0.x * 16 + lane], acc);
            acc = fmaf(__uint_as_float(e1.y), g_h3[(size_t)e1.x * 16 + lane], acc);
            acc = fmaf(__uint_as_float(e2.y), g_h3[(size_t)e2.x * 16 + lane], acc);
            acc = fmaf(__uint_as_float(e3.y), g_h3[(size_t)e3.x * 16 + lane], acc);
        }
    }
    for (; j < end; j++) {
        uint2 ed = g_edge[j];
        if (active) acc = fmaf(__uint_as_float(ed.y), g_h3[(size_t)ed.x * 16 + lane], acc);
    }

    int g = batch[gw];
    if (active) {
        acc = fmaf(acc, di, b3[lane]);
        atomicAdd(&g_psum[g * CCNT + lane], acc);
    }
    if (lane == 0) atomicAdd(&g_pcnt[g], 1.0f);
}

// ---------------- final: mean + log_softmax ----------------
__global__ void k_finalize(float* __restrict__ out) {
    int g = threadIdx.x;
    if (g >= GCNT) return;
    float c = fmaxf(g_pcnt[g], 1.0f);
    float v[CCNT];
    float m = -1e30f;
#pragma unroll
    for (int j = 0; j < CCNT; j++) {
        v[j] = g_psum[g * CCNT + j] / c;
        m = fmaxf(m, v[j]);
    }
    float s = 0.0f;
#pragma unroll
    for (int j = 0; j < CCNT; j++) s += expf(v[j] - m);
    float lse = logf(s) + m;
#pragma unroll
    for (int j = 0; j < CCNT; j++) out[g * CCNT + j] = v[j] - lse;
}

// ---------------- launch ----------------
extern "C" void kernel_launch(void* const* d_in, const int* in_sizes, int n_in,
                              void* d_out, int out_size) {
    const float* x    = (const float*)d_in[0];
    const int*   ei   = (const int*)d_in[1];
    const float* ea   = (const float*)d_in[2];
    const int*   bat  = (const int*)d_in[3];
    const float* W1   = (const float*)d_in[4];
    const float* b1   = (const float*)d_in[5];
    const float* W2   = (const float*)d_in[6];
    const float* b2   = (const float*)d_in[7];
    const float* W3   = (const float*)d_in[8];
    const float* b3   = (const float*)d_in[9];
    float* out = (float*)d_out;

    int n = in_sizes[0] / HDIM;   // 50000
    int e = in_sizes[1] / 2;      // 800000
    const int* src = ei;
    const int* dst = ei + e;

    unsigned* ghb;
    float* gagg;
    cudaGetSymbolAddress((void**)&ghb, g_hb);
    cudaGetSymbolAddress((void**)&gagg, g_agg);

    int nb = (n + SCAN_BLK - 1) / SCAN_BLK;
    int gemmBlocks = (n + 127) / 128;
    int aggBlocks256 = (n * 32 + 255) / 256;
    int aggBlocks512 = (n * 32 + 511) / 512;

    cudaStream_t s0 = (cudaStream_t)0;

    cudaStream_t s2;
    cudaStreamCreateWithFlags(&s2, cudaStreamNonBlocking);
    cudaEvent_t evFork, evJoin;
    cudaEventCreateWithFlags(&evFork, cudaEventDisableTiming);
    cudaEventCreateWithFlags(&evJoin, cudaEventDisableTiming);

    cudaEventRecord(evFork, s0);
    cudaStreamWaitEvent(s2, evFork, 0);
    sgemm128_tf32<<<gemmBlocks, 256, 0, s2>>>(x, W1, ghb, n);   // h = x@W1 (bf16 packed)
    cudaEventRecord(evJoin, s2);

    k_init<<<(n + 255) / 256, 256, 0, s0>>>(n);
    k_count<<<(e + 255) / 256, 256, 0, s0>>>(dst, ea, e);
    k_scan1<<<nb, SCAN_BLK, 0, s0>>>(n);
    k_scan3<<<nb, SCAN_BLK, 0, s0>>>(n, e, nb);
    k_scatter<<<(e + 255) / 256, 256, 0, s0>>>(src, dst, ea, e);

    cudaStreamWaitEvent(s0, evJoin, 0);
    agg_h128<<<aggBlocks256, 256, 0, s0>>>(ghb, gagg, b1, n);

    sgemm128_tf32<<<gemmBlocks, 256, 0, s0>>>(gagg, W2, ghb, n);
    agg_h128_w3<<<aggBlocks512, 512, 0, s0>>>(ghb, b2, W3, n);

    agg_c16_pool<<<aggBlocks256, 256, 0, s0>>>(bat, b3, n);
    k_finalize<<<1, 128, 0, s0>>>(out);
    // NOTE: s2/events intentionally not destroyed — kernel_launch is invoked
    // only for the correctness run and one graph capture.
}